// round 13
// baseline (speedup 1.0000x reference)
#include <cuda_runtime.h>
#include <cstdint>

#define N_PTS 65536
#define HID   256
#define NB    4
#define PPB   16384
#define TOPK  4096

// ---------------- packed fp32x2 helpers (bit-exact IEEE fp32 per lane) ----
__device__ __forceinline__ unsigned long long pack2(float lo, float hi)
{
    unsigned long long r;
    asm("mov.b64 %0, {%1, %2};" : "=l"(r) : "f"(lo), "f"(hi));
    return r;
}
__device__ __forceinline__ void unpack2(unsigned long long v, float& lo, float& hi)
{
    asm("mov.b64 {%0, %1}, %2;" : "=f"(lo), "=f"(hi) : "l"(v));
}
__device__ __forceinline__ unsigned long long ffma2(
    unsigned long long a, unsigned long long b, unsigned long long c)
{
    unsigned long long d;
    asm("fma.rn.f32x2 %0, %1, %2, %3;" : "=l"(d) : "l"(a), "l"(b), "l"(c));
    return d;
}

// ---------------- scratch (device globals; no allocation) ----------------
__device__ float g_pf[N_PTS * HID];            // 64 MiB point features
__device__ float g_s[N_PTS];
__device__ double g_partial[2 * 1024];         // per-block (sum, sumsq) in fp64
__device__ float g_scores[N_PTS];
__device__ float g_e[N_PTS];                   // unnormalized softmax exp
__device__ float g_bn[4];                      // mu, r, gamma, beta
__device__ float g_bmax[64];
__device__ float g_bsum[64];
__device__ unsigned long long g_keys[N_PTS];   // sort keys
__device__ float g_coef[NB * TOPK];
__device__ int   g_gidx[NB * TOPK];

// ---------------- K1: fused point MLP, cuBLAS-order fp32, FFMA2 inner ----
// 64-row x 128-col tiles (grid 2048) to kill wave quantization; per-element
// accumulation chain identical to the 128-row version -> bit-identical g_pf.
__global__ void __launch_bounds__(256, 2) k_mlp(
    const float* __restrict__ pts, const float* __restrict__ w1,
    const float* __restrict__ b1,  const float* __restrict__ w2,
    const float* __restrict__ b2)
{
    __shared__ float sW1[4 * HID];
    __shared__ float sB1[HID];
    __shared__ float sPts[4][68];
    __shared__ __align__(16) float sA[32][68];
    __shared__ __align__(16) float sB[32][132];

    const int tid  = threadIdx.x;
    const int row0 = blockIdx.x * 64;
    const int col0 = blockIdx.y * 128;
    const int tx = tid & 15, ty = tid >> 4;

    for (int i = tid; i < 4 * HID; i += 256) sW1[i] = w1[i];
    sB1[tid] = b1[tid];
    // 64 rows x 4 dims = 256 floats
    sPts[tid & 3][tid >> 2] = pts[row0 * 4 + tid];
    __syncthreads();

    unsigned long long acc2[4][4];
#pragma unroll
    for (int i = 0; i < 4; i++)
#pragma unroll
        for (int j = 0; j < 4; j++) acc2[i][j] = 0ull;

    for (int kc = 0; kc < HID; kc += 32) {
        __syncthreads();
        // A chunk: h[r][kc+k] = relu((pts . w1col) + b1) — dot first, bias after
#pragma unroll
        for (int it = 0; it < 8; it++) {
            int lin = tid + it * 256;
            int k = lin >> 6, r = lin & 63;
            float v = 0.f;
#pragma unroll
            for (int j = 0; j < 4; j++) v = fmaf(sPts[j][r], sW1[j * HID + kc + k], v);
            v += sB1[kc + k];
            sA[k][r] = fmaxf(v, 0.f);
        }
        // B chunk: w2[kc+k][col0+c]
#pragma unroll
        for (int it = 0; it < 4; it++) {
            int lin = tid + it * 256;         // float4 index 0..1023
            int k = lin >> 5, c4 = lin & 31;
            float4 v = *(const float4*)&w2[(kc + k) * HID + col0 + c4 * 4];
            *(float4*)&sB[k][c4 * 4] = v;
        }
        __syncthreads();
#pragma unroll
        for (int k = 0; k < 32; k++) {
            float a[4];
            *(float4*)&a[0] = *(const float4*)&sA[k][ty * 4];
            ulonglong2 bv0 = *(const ulonglong2*)&sB[k][tx * 8];
            ulonglong2 bv1 = *(const ulonglong2*)&sB[k][tx * 8 + 4];
#pragma unroll
            for (int i = 0; i < 4; i++) {
                unsigned long long ad = pack2(a[i], a[i]);
                acc2[i][0] = ffma2(ad, bv0.x, acc2[i][0]);
                acc2[i][1] = ffma2(ad, bv0.y, acc2[i][1]);
                acc2[i][2] = ffma2(ad, bv1.x, acc2[i][2]);
                acc2[i][3] = ffma2(ad, bv1.y, acc2[i][3]);
            }
        }
    }
    float bb[8];
#pragma unroll
    for (int j = 0; j < 8; j++) bb[j] = b2[col0 + tx * 8 + j];
#pragma unroll
    for (int i = 0; i < 4; i++) {
        int r = row0 + ty * 4 + i;
        float c[8];
#pragma unroll
        for (int j2 = 0; j2 < 4; j2++) unpack2(acc2[i][j2], c[2 * j2], c[2 * j2 + 1]);
        float4 o0, o1;
        o0.x = fmaxf(c[0] + bb[0], 0.f);
        o0.y = fmaxf(c[1] + bb[1], 0.f);
        o0.z = fmaxf(c[2] + bb[2], 0.f);
        o0.w = fmaxf(c[3] + bb[3], 0.f);
        o1.x = fmaxf(c[4] + bb[4], 0.f);
        o1.y = fmaxf(c[5] + bb[5], 0.f);
        o1.z = fmaxf(c[6] + bb[6], 0.f);
        o1.w = fmaxf(c[7] + bb[7], 0.f);
        *(float4*)&g_pf[r * HID + col0 + tx * 8]     = o0;
        *(float4*)&g_pf[r * HID + col0 + tx * 8 + 4] = o1;
    }
}

// ---------------- K2: s[row] = sequential-k fp32 dot (pf row . ws) + bs ----
__global__ void __launch_bounds__(64) k_srow(
    const float* __restrict__ ws, const float* __restrict__ bs)
{
    __shared__ __align__(16) float tile[64][260];
    __shared__ float sWs[HID];
    __shared__ double wS[2], wS2[2];
    const int tid = threadIdx.x;             // 64
    const int row0 = blockIdx.x * 64;

    for (int i = tid; i < HID; i += 64) sWs[i] = ws[i];
#pragma unroll 8
    for (int it = 0; it < 64; it++) {
        int idx = tid + it * 64;             // float4 idx 0..4095
        int r = idx >> 6, c4 = idx & 63;
        float4 v = *(const float4*)&g_pf[(row0 + r) * HID + c4 * 4];
        *(float4*)&tile[r][c4 * 4] = v;
    }
    __syncthreads();

    float d = 0.f;
#pragma unroll 16
    for (int c4 = 0; c4 < 64; c4++) {
        float4 a = *(const float4*)&tile[tid][c4 * 4];
        d = fmaf(a.x, sWs[c4 * 4 + 0], d);
        d = fmaf(a.y, sWs[c4 * 4 + 1], d);
        d = fmaf(a.z, sWs[c4 * 4 + 2], d);
        d = fmaf(a.w, sWs[c4 * 4 + 3], d);
    }
    float sv = d + bs[0];
    g_s[row0 + tid] = sv;

    double a = (double)sv, b = (double)sv * (double)sv;
#pragma unroll
    for (int o = 16; o > 0; o >>= 1) {
        a += __shfl_down_sync(0xffffffffu, a, o);
        b += __shfl_down_sync(0xffffffffu, b, o);
    }
    int lane = tid & 31, w = tid >> 5;
    if (lane == 0) { wS[w] = a; wS2[w] = b; }
    __syncthreads();
    if (tid == 0) {
        g_partial[blockIdx.x * 2]     = wS[0] + wS[1];
        g_partial[blockIdx.x * 2 + 1] = wS2[0] + wS2[1];
    }
}

// ---------------- block reduce helpers (1024 threads) ----------------
__device__ __forceinline__ float blk_add(float v, float* red)
{
    int tid = threadIdx.x;
    red[tid] = v; __syncthreads();
    for (int o = 512; o > 0; o >>= 1) { if (tid < o) red[tid] += red[tid + o]; __syncthreads(); }
    float r = red[0]; __syncthreads();
    return r;
}
__device__ __forceinline__ float blk_max(float v, float* red)
{
    int tid = threadIdx.x;
    red[tid] = v; __syncthreads();
    for (int o = 512; o > 0; o >>= 1) { if (tid < o) red[tid] = fmaxf(red[tid], red[tid + o]); __syncthreads(); }
    float r = red[0]; __syncthreads();
    return r;
}
__device__ __forceinline__ double blk_addd(double v, double* red)
{
    int tid = threadIdx.x;
    red[tid] = v; __syncthreads();
    for (int o = 512; o > 0; o >>= 1) { if (tid < o) red[tid] += red[tid + o]; __syncthreads(); }
    double r = red[0]; __syncthreads();
    return r;
}

// ---------------- K3a: BN stats reduce (fp64, 1 CTA) ----------------
__global__ void k_bn(const float* __restrict__ gamma, const float* __restrict__ beta)
{
    __shared__ double redd[1024];
    int tid = threadIdx.x;
    double a = g_partial[tid * 2];
    double b = g_partial[tid * 2 + 1];
    double S  = blk_addd(a, redd);
    double S2 = blk_addd(b, redd);
    if (tid == 0) {
        double mu = S / (double)N_PTS;
        double var = S2 / (double)N_PTS - mu * mu;
        float varf = (float)var;
        g_bn[0] = (float)mu;
        g_bn[1] = (float)(1.0 / sqrt((double)varf + 1e-5));
        g_bn[2] = gamma[0];
        g_bn[3] = beta[0];
    }
}

// ---------------- K3b: scores (parallel) + per-block max ----------------
__global__ void k_score()
{
    __shared__ float red[1024];
    int tid = threadIdx.x;
    int idx = blockIdx.x * 1024 + tid;
    float mu = g_bn[0], r = g_bn[1], ga = g_bn[2], be = g_bn[3];
    float sc = fmaxf(((g_s[idx] - mu) * r) * ga + be, 0.f);
    g_scores[idx] = sc;
    float m = blk_max(sc, red);
    if (tid == 0) g_bmax[blockIdx.x] = m;
}

// ---------------- K3c: e = expf(sc/0.1 - ymax) + block sums ----------------
__global__ void k_exp()
{
    __shared__ float red[1024];
    __shared__ float sYmax;
    int tid = threadIdx.x;
    if (tid < 32) {
        float m = fmaxf(g_bmax[tid], g_bmax[tid + 32]);
#pragma unroll
        for (int o = 16; o > 0; o >>= 1) m = fmaxf(m, __shfl_down_sync(0xffffffffu, m, o));
        if (tid == 0) sYmax = m / 0.1f;
    }
    __syncthreads();
    float ymax = sYmax;
    int idx = blockIdx.x * 1024 + tid;
    float e = expf(g_scores[idx] / 0.1f - ymax);
    g_e[idx] = e;
    float s = blk_add(e, red);
    if (tid == 0) g_bsum[blockIdx.x] = s;
}

// ---------------- K4a: Z (identical tree) + keys + local bitonic sort ----
__global__ void k_sort1()
{
    __shared__ unsigned long long s[2048];
    __shared__ float sZ;
    int base = blockIdx.x * 2048;
    int t = threadIdx.x;                 // 1024
    if (t < 32) {
        float a = g_bsum[t] + g_bsum[t + 32];
#pragma unroll
        for (int o = 16; o > 0; o >>= 1) a += __shfl_down_sync(0xffffffffu, a, o);
        if (t == 0) sZ = a;
    }
    __syncthreads();
    float Z = sZ;
    {
        float w0 = g_e[base + t] / Z;
        float w1v = g_e[base + t + 1024] / Z;
        s[t] = ((unsigned long long)(~__float_as_uint(w0)) << 32)
             | (unsigned int)((base + t) & (PPB - 1));
        s[t + 1024] = ((unsigned long long)(~__float_as_uint(w1v)) << 32)
             | (unsigned int)((base + t + 1024) & (PPB - 1));
    }
    for (int k = 2; k <= 2048; k <<= 1) {
        for (int j = k >> 1; j > 0; j >>= 1) {
            __syncthreads();
            int i = ((t & ~(j - 1)) << 1) | (t & (j - 1));
            int p = i | j;
            int li = (base + i) & (PPB - 1);
            bool asc = ((li & k) == 0);
            unsigned long long x = s[i], y = s[p];
            if ((x > y) == asc) { s[i] = y; s[p] = x; }
        }
    }
    __syncthreads();
    g_keys[base + t] = s[t];
    g_keys[base + t + 1024] = s[t + 1024];
}

// ---------------- K4c: single global CE pass (phase 4096, j=2048) ----------
__global__ void k_global_ce(int k, int j)
{
    int t = blockIdx.x * blockDim.x + threadIdx.x;   // 32768
    int b = t >> 13;
    int q = t & 8191;
    int i = ((q & ~(j - 1)) << 1) | (q & (j - 1));
    int gi = b * PPB + i;
    bool asc = ((i & k) == 0);
    unsigned long long x = g_keys[gi], y = g_keys[gi + j];
    if ((x > y) == asc) { g_keys[gi] = y; g_keys[gi + j] = x; }
}

// ---------------- K4e: fused CE passes j=4096,2048 of phase k=8192 ----------
__global__ void k_ce2()
{
    int t = blockIdx.x * blockDim.x + threadIdx.x;   // 16384
    int seg = t >> 12;
    int q = t & 4095;
    int i = (q & 2047) | ((q >> 11) << 13);          // bits 2048,4096 clear
    int g0 = seg * PPB + i;
    unsigned long long a = g_keys[g0];
    unsigned long long b = g_keys[g0 + 2048];
    unsigned long long c = g_keys[g0 + 4096];
    unsigned long long d = g_keys[g0 + 6144];
    bool asc = ((i & 8192) == 0);
    unsigned long long tswap;
    if ((a > c) == asc) { tswap = a; a = c; c = tswap; }
    if ((b > d) == asc) { tswap = b; b = d; d = tswap; }
    if ((a > b) == asc) { tswap = a; a = b; b = tswap; }
    if ((c > d) == asc) { tswap = c; c = d; d = tswap; }
    g_keys[g0]        = a;
    g_keys[g0 + 2048] = b;
    g_keys[g0 + 4096] = c;
    g_keys[g0 + 6144] = d;
}

// ---------------- K4f: fused CE passes j=8192,4096,2048 of phase k=16384 ----
__global__ void k_ce3()
{
    int t = blockIdx.x * blockDim.x + threadIdx.x;   // 8192
    int seg = t >> 11;
    int q = t & 2047;
    int g0 = seg * PPB + q;
    unsigned long long v[8];
#pragma unroll
    for (int m = 0; m < 8; m++) v[m] = g_keys[g0 + m * 2048];
    unsigned long long tswap;
#define CEA(x, y) if (v[x] > v[y]) { tswap = v[x]; v[x] = v[y]; v[y] = tswap; }
    CEA(0, 4) CEA(1, 5) CEA(2, 6) CEA(3, 7)
    CEA(0, 2) CEA(1, 3) CEA(4, 6) CEA(5, 7)
    CEA(0, 1) CEA(2, 3) CEA(4, 5) CEA(6, 7)
#undef CEA
#pragma unroll
    for (int m = 0; m < 8; m++) g_keys[g0 + m * 2048] = v[m];
}

// ---------------- K4d: local merge (j<=1024 within phase k) ----------------
__global__ void k_merge_local(int k)
{
    __shared__ unsigned long long s[2048];
    int base = blockIdx.x * 2048;
    int t = threadIdx.x;
    s[t] = g_keys[base + t];
    s[t + 1024] = g_keys[base + t + 1024];
    for (int j = 1024; j > 0; j >>= 1) {
        __syncthreads();
        int i = ((t & ~(j - 1)) << 1) | (t & (j - 1));
        int p = i | j;
        int li = (base + i) & (PPB - 1);
        bool asc = ((li & k) == 0);
        unsigned long long x = s[i], y = s[p];
        if ((x > y) == asc) { s[i] = y; s[p] = x; }
    }
    __syncthreads();
    g_keys[base + t] = s[t];
    g_keys[base + t + 1024] = s[t + 1024];
}

// ---------------- K5: select top-K per batch + normalized coefficients ----
__global__ void k_select()
{
    __shared__ float red[1024];
    __shared__ float sDen;
    int b = blockIdx.x, tid = threadIdx.x;   // 4 x 1024
    float w4[4];
    float loc = 0.f;
#pragma unroll
    for (int i = 0; i < 4; i++) {
        int r = tid + i * 1024;
        unsigned long long kk = g_keys[b * PPB + r];
        int li = (int)(unsigned int)(kk & 0xffffffffull);
        float w = __uint_as_float(~(unsigned int)(kk >> 32));
        g_gidx[b * TOPK + r] = b * PPB + li;
        w4[i] = w; loc += w;
    }
    float Sb = blk_add(loc, red);
    if (tid == 0) sDen = Sb + 1e-8f;
    __syncthreads();
    float den = sDen;
#pragma unroll
    for (int i = 0; i < 4; i++)
        g_coef[b * TOPK + tid + i * 1024] = w4[i] / den;
}

// ---------------- K7: processor MLP on selected rows, FFMA2 inner ----
__global__ void __launch_bounds__(256, 2) k_proc(
    const float* __restrict__ wp1, const float* __restrict__ bp1,
    const float* __restrict__ wp2, const float* __restrict__ bp2,
    float* __restrict__ out)
{
    __shared__ __align__(16) float sA[32][68];
    __shared__ __align__(16) float sB[32][260];
    __shared__ float sWp2[HID * 4];
    __shared__ float sBp1[HID];
    __shared__ float sC[64];
    __shared__ int   sG[64];

    int tid = threadIdx.x;
    int row0 = blockIdx.x * 64;
    int tx = tid & 15, ty = tid >> 4;

    for (int i = tid; i < HID * 4; i += 256) sWp2[i] = wp2[i];
    sBp1[tid] = bp1[tid];
    if (tid < 64) { sC[tid] = g_coef[row0 + tid]; sG[tid] = g_gidx[row0 + tid]; }
    __syncthreads();

    unsigned long long acc2[4][8];
#pragma unroll
    for (int i = 0; i < 4; i++)
#pragma unroll
        for (int j = 0; j < 8; j++) acc2[i][j] = 0ull;

    for (int kc = 0; kc < HID; kc += 32) {
        __syncthreads();
#pragma unroll
        for (int it = 0; it < 8; it++) {
            int lin = tid + it * 256;        // 0..2047
            int r = lin >> 5, k = lin & 31;
            sA[k][r] = g_pf[sG[r] * HID + kc + k] * sC[r];
        }
#pragma unroll
        for (int it = 0; it < 8; it++) {
            int lin = tid + it * 256;        // float4 index 0..2047
            int k = lin >> 6, c4 = lin & 63;
            *(float4*)&sB[k][c4 * 4] = *(const float4*)&wp1[(kc + k) * HID + c4 * 4];
        }
        __syncthreads();
#pragma unroll
        for (int k = 0; k < 32; k++) {
            float a[4];
            *(float4*)&a[0] = *(const float4*)&sA[k][ty * 4];
            ulonglong2 bv0 = *(const ulonglong2*)&sB[k][tx * 16];
            ulonglong2 bv1 = *(const ulonglong2*)&sB[k][tx * 16 + 4];
            ulonglong2 bv2 = *(const ulonglong2*)&sB[k][tx * 16 + 8];
            ulonglong2 bv3 = *(const ulonglong2*)&sB[k][tx * 16 + 12];
#pragma unroll
            for (int i = 0; i < 4; i++) {
                unsigned long long ad = pack2(a[i], a[i]);
                acc2[i][0] = ffma2(ad, bv0.x, acc2[i][0]);
                acc2[i][1] = ffma2(ad, bv0.y, acc2[i][1]);
                acc2[i][2] = ffma2(ad, bv1.x, acc2[i][2]);
                acc2[i][3] = ffma2(ad, bv1.y, acc2[i][3]);
                acc2[i][4] = ffma2(ad, bv2.x, acc2[i][4]);
                acc2[i][5] = ffma2(ad, bv2.y, acc2[i][5]);
                acc2[i][6] = ffma2(ad, bv3.x, acc2[i][6]);
                acc2[i][7] = ffma2(ad, bv3.y, acc2[i][7]);
            }
        }
    }
#pragma unroll
    for (int i = 0; i < 4; i++) {
        int rl = ty * 4 + i;
        float p0 = 0.f, p1 = 0.f, p2 = 0.f, p3 = 0.f;
#pragma unroll
        for (int j2 = 0; j2 < 8; j2++) {
            float c0, c1;
            unpack2(acc2[i][j2], c0, c1);
            int col0i = tx * 16 + 2 * j2;
            float v0 = fmaxf(c0 + sBp1[col0i], 0.f);
            float v1 = fmaxf(c1 + sBp1[col0i + 1], 0.f);
            p0 = fmaf(v0, sWp2[col0i * 4 + 0], p0);
            p1 = fmaf(v0, sWp2[col0i * 4 + 1], p1);
            p2 = fmaf(v0, sWp2[col0i * 4 + 2], p2);
            p3 = fmaf(v0, sWp2[col0i * 4 + 3], p3);
            p0 = fmaf(v1, sWp2[(col0i + 1) * 4 + 0], p0);
            p1 = fmaf(v1, sWp2[(col0i + 1) * 4 + 1], p1);
            p2 = fmaf(v1, sWp2[(col0i + 1) * 4 + 2], p2);
            p3 = fmaf(v1, sWp2[(col0i + 1) * 4 + 3], p3);
        }
#pragma unroll
        for (int o = 8; o > 0; o >>= 1) {
            p0 += __shfl_down_sync(0xffffffffu, p0, o, 16);
            p1 += __shfl_down_sync(0xffffffffu, p1, o, 16);
            p2 += __shfl_down_sync(0xffffffffu, p2, o, 16);
            p3 += __shfl_down_sync(0xffffffffu, p3, o, 16);
        }
        if (tx == 0) {
            int row = row0 + rl;
            float4 o4;
            o4.x = p0 + bp2[0];
            o4.y = p1 + bp2[1];
            o4.z = p2 + bp2[2];
            o4.w = p3 + bp2[3];
            *(float4*)&out[row * 4] = o4;
        }
    }
}

// ---------------- launch ----------------
extern "C" void kernel_launch(void* const* d_in, const int* in_sizes, int n_in,
                              void* d_out, int out_size)
{
    const float* pts   = (const float*)d_in[0];
    const float* w1    = (const float*)d_in[1];
    const float* b1    = (const float*)d_in[2];
    const float* w2    = (const float*)d_in[3];
    const float* b2    = (const float*)d_in[4];
    const float* ws    = (const float*)d_in[5];
    const float* bs    = (const float*)d_in[6];
    const float* gamma = (const float*)d_in[7];
    const float* beta  = (const float*)d_in[8];
    const float* wp1   = (const float*)d_in[9];
    const float* bp1   = (const float*)d_in[10];
    const float* wp2   = (const float*)d_in[11];
    const float* bp2   = (const float*)d_in[12];
    float* out = (float*)d_out;

    dim3 g1(1024, 2);
    k_mlp<<<g1, 256>>>(pts, w1, b1, w2, b2);
    k_srow<<<1024, 64>>>(ws, bs);

    k_bn<<<1, 1024>>>(gamma, beta);
    k_score<<<64, 1024>>>();
    k_exp<<<64, 1024>>>();

    k_sort1<<<32, 1024>>>();
    k_global_ce<<<128, 256>>>(4096, 2048);
    k_merge_local<<<32, 1024>>>(4096);
    k_ce2<<<64, 256>>>();
    k_merge_local<<<32, 1024>>>(8192);
    k_ce3<<<32, 256>>>();
    k_merge_local<<<32, 1024>>>(16384);

    k_select<<<NB, 1024>>>();
    k_proc<<<256, 256>>>(wp1, bp1, wp2, bp2, out);
}

// round 15
// speedup vs baseline: 1.2528x; 1.2528x over previous
#include <cuda_runtime.h>
#include <cstdint>

#define N_PTS 65536
#define HID   256
#define NB    4
#define PPB   16384
#define TOPK  4096

// ---------------- packed fp32x2 helpers (bit-exact IEEE fp32 per lane) ----
__device__ __forceinline__ unsigned long long pack2(float lo, float hi)
{
    unsigned long long r;
    asm("mov.b64 %0, {%1, %2};" : "=l"(r) : "f"(lo), "f"(hi));
    return r;
}
__device__ __forceinline__ void unpack2(unsigned long long v, float& lo, float& hi)
{
    asm("mov.b64 {%0, %1}, %2;" : "=f"(lo), "=f"(hi) : "l"(v));
}
__device__ __forceinline__ unsigned long long ffma2(
    unsigned long long a, unsigned long long b, unsigned long long c)
{
    unsigned long long d;
    asm("fma.rn.f32x2 %0, %1, %2, %3;" : "=l"(d) : "l"(a), "l"(b), "l"(c));
    return d;
}

// ---------------- scratch (device globals; no allocation) ----------------
__device__ float g_pf[N_PTS * HID];            // 64 MiB point features
__device__ float g_s[N_PTS];
__device__ double g_partial[2 * 1024];         // per-block (sum, sumsq) in fp64
__device__ float g_scores[N_PTS];
__device__ float g_e[N_PTS];                   // unnormalized softmax exp
__device__ float g_scalars[4];                 // [0]=smax, [1]=Z, [2]=ymax
__device__ float g_bn[4];                      // mu, r, gamma, beta
__device__ float g_bmax[64];
__device__ float g_bsum[64];
__device__ unsigned long long g_keys[N_PTS];   // sort keys
__device__ float g_coef[NB * TOPK];
__device__ int   g_gidx[NB * TOPK];

// ---------------- K1: fused point MLP, cuBLAS-order fp32, FFMA2 inner ----
__global__ void __launch_bounds__(256, 2) k_mlp(
    const float* __restrict__ pts, const float* __restrict__ w1,
    const float* __restrict__ b1,  const float* __restrict__ w2,
    const float* __restrict__ b2)
{
    __shared__ float sW1[4 * HID];
    __shared__ float sB1[HID];
    __shared__ float sPts[4][132];
    __shared__ __align__(16) float sA[32][132];
    __shared__ __align__(16) float sB[32][132];

    const int tid  = threadIdx.x;
    const int row0 = blockIdx.x * 128;
    const int col0 = blockIdx.y * 128;
    const int tx = tid & 15, ty = tid >> 4;

    for (int i = tid; i < 4 * HID; i += 256) sW1[i] = w1[i];
    sB1[tid] = b1[tid];
    for (int i = tid; i < 512; i += 256) {
        float v = pts[row0 * 4 + i];
        sPts[i & 3][i >> 2] = v;
    }
    __syncthreads();

    unsigned long long acc2[8][4];
#pragma unroll
    for (int i = 0; i < 8; i++)
#pragma unroll
        for (int j = 0; j < 4; j++) acc2[i][j] = 0ull;

    for (int kc = 0; kc < HID; kc += 32) {
        __syncthreads();
        // A chunk: h[r][kc+k] = relu((pts . w1col) + b1) — dot first, bias after
#pragma unroll
        for (int it = 0; it < 16; it++) {
            int lin = tid + it * 256;
            int k = lin >> 7, r = lin & 127;
            float v = 0.f;
#pragma unroll
            for (int j = 0; j < 4; j++) v = fmaf(sPts[j][r], sW1[j * HID + kc + k], v);
            v += sB1[kc + k];
            sA[k][r] = fmaxf(v, 0.f);
        }
        // B chunk: w2[kc+k][col0+c]
#pragma unroll
        for (int it = 0; it < 4; it++) {
            int lin = tid + it * 256;         // float4 index 0..1023
            int k = lin >> 5, c4 = lin & 31;
            float4 v = *(const float4*)&w2[(kc + k) * HID + col0 + c4 * 4];
            *(float4*)&sB[k][c4 * 4] = v;
        }
        __syncthreads();
#pragma unroll
        for (int k = 0; k < 32; k++) {
            float a[8];
            *(float4*)&a[0] = *(const float4*)&sA[k][ty * 8];
            *(float4*)&a[4] = *(const float4*)&sA[k][ty * 8 + 4];
            ulonglong2 bv0 = *(const ulonglong2*)&sB[k][tx * 8];
            ulonglong2 bv1 = *(const ulonglong2*)&sB[k][tx * 8 + 4];
#pragma unroll
            for (int i = 0; i < 8; i++) {
                unsigned long long ad = pack2(a[i], a[i]);
                acc2[i][0] = ffma2(ad, bv0.x, acc2[i][0]);
                acc2[i][1] = ffma2(ad, bv0.y, acc2[i][1]);
                acc2[i][2] = ffma2(ad, bv1.x, acc2[i][2]);
                acc2[i][3] = ffma2(ad, bv1.y, acc2[i][3]);
            }
        }
    }
    float bb[8];
#pragma unroll
    for (int j = 0; j < 8; j++) bb[j] = b2[col0 + tx * 8 + j];
#pragma unroll
    for (int i = 0; i < 8; i++) {
        int r = row0 + ty * 8 + i;
        float c[8];
#pragma unroll
        for (int j2 = 0; j2 < 4; j2++) unpack2(acc2[i][j2], c[2 * j2], c[2 * j2 + 1]);
        float4 o0, o1;
        o0.x = fmaxf(c[0] + bb[0], 0.f);
        o0.y = fmaxf(c[1] + bb[1], 0.f);
        o0.z = fmaxf(c[2] + bb[2], 0.f);
        o0.w = fmaxf(c[3] + bb[3], 0.f);
        o1.x = fmaxf(c[4] + bb[4], 0.f);
        o1.y = fmaxf(c[5] + bb[5], 0.f);
        o1.z = fmaxf(c[6] + bb[6], 0.f);
        o1.w = fmaxf(c[7] + bb[7], 0.f);
        *(float4*)&g_pf[r * HID + col0 + tx * 8]     = o0;
        *(float4*)&g_pf[r * HID + col0 + tx * 8 + 4] = o1;
    }
}

// ---------------- K2: s[row] = sequential-k fp32 dot (pf row . ws) + bs ----
__global__ void __launch_bounds__(64) k_srow(
    const float* __restrict__ ws, const float* __restrict__ bs)
{
    __shared__ __align__(16) float tile[64][260];
    __shared__ float sWs[HID];
    __shared__ double wS[2], wS2[2];
    const int tid = threadIdx.x;             // 64
    const int row0 = blockIdx.x * 64;

    for (int i = tid; i < HID; i += 64) sWs[i] = ws[i];
#pragma unroll 8
    for (int it = 0; it < 64; it++) {
        int idx = tid + it * 64;             // float4 idx 0..4095
        int r = idx >> 6, c4 = idx & 63;
        float4 v = *(const float4*)&g_pf[(row0 + r) * HID + c4 * 4];
        *(float4*)&tile[r][c4 * 4] = v;
    }
    __syncthreads();

    float d = 0.f;
#pragma unroll 16
    for (int c4 = 0; c4 < 64; c4++) {
        float4 a = *(const float4*)&tile[tid][c4 * 4];
        d = fmaf(a.x, sWs[c4 * 4 + 0], d);
        d = fmaf(a.y, sWs[c4 * 4 + 1], d);
        d = fmaf(a.z, sWs[c4 * 4 + 2], d);
        d = fmaf(a.w, sWs[c4 * 4 + 3], d);
    }
    float sv = d + bs[0];
    g_s[row0 + tid] = sv;

    double a = (double)sv, b = (double)sv * (double)sv;
#pragma unroll
    for (int o = 16; o > 0; o >>= 1) {
        a += __shfl_down_sync(0xffffffffu, a, o);
        b += __shfl_down_sync(0xffffffffu, b, o);
    }
    int lane = tid & 31, w = tid >> 5;
    if (lane == 0) { wS[w] = a; wS2[w] = b; }
    __syncthreads();
    if (tid == 0) {
        g_partial[blockIdx.x * 2]     = wS[0] + wS[1];
        g_partial[blockIdx.x * 2 + 1] = wS2[0] + wS2[1];
    }
}

// ---------------- block reduce helpers (1024 threads) ----------------
__device__ __forceinline__ float blk_add(float v, float* red)
{
    int tid = threadIdx.x;
    red[tid] = v; __syncthreads();
    for (int o = 512; o > 0; o >>= 1) { if (tid < o) red[tid] += red[tid + o]; __syncthreads(); }
    float r = red[0]; __syncthreads();
    return r;
}
__device__ __forceinline__ float blk_max(float v, float* red)
{
    int tid = threadIdx.x;
    red[tid] = v; __syncthreads();
    for (int o = 512; o > 0; o >>= 1) { if (tid < o) red[tid] = fmaxf(red[tid], red[tid + o]); __syncthreads(); }
    float r = red[0]; __syncthreads();
    return r;
}
__device__ __forceinline__ double blk_addd(double v, double* red)
{
    int tid = threadIdx.x;
    red[tid] = v; __syncthreads();
    for (int o = 512; o > 0; o >>= 1) { if (tid < o) red[tid] += red[tid + o]; __syncthreads(); }
    double r = red[0]; __syncthreads();
    return r;
}

// ---------------- K3a: BN stats reduce (fp64, 1 CTA) ----------------
__global__ void k_bn(const float* __restrict__ gamma, const float* __restrict__ beta)
{
    __shared__ double redd[1024];
    int tid = threadIdx.x;
    double a = g_partial[tid * 2];
    double b = g_partial[tid * 2 + 1];
    double S  = blk_addd(a, redd);
    double S2 = blk_addd(b, redd);
    if (tid == 0) {
        double mu = S / (double)N_PTS;
        double var = S2 / (double)N_PTS - mu * mu;
        float varf = (float)var;
        g_bn[0] = (float)mu;
        g_bn[1] = (float)(1.0 / sqrt((double)varf + 1e-5));
        g_bn[2] = gamma[0];
        g_bn[3] = beta[0];
    }
}

// ---------------- K3b: scores (parallel) + per-block max ----------------
__global__ void k_score()
{
    __shared__ float red[1024];
    int tid = threadIdx.x;
    int idx = blockIdx.x * 1024 + tid;
    float mu = g_bn[0], r = g_bn[1], ga = g_bn[2], be = g_bn[3];
    float sc = fmaxf(((g_s[idx] - mu) * r) * ga + be, 0.f);
    g_scores[idx] = sc;
    float m = blk_max(sc, red);
    if (tid == 0) g_bmax[blockIdx.x] = m;
}

// ---------------- K3c: global max of 64 block maxes ----------------
__global__ void k_gmax()
{
    int lane = threadIdx.x;                  // 32
    float m = fmaxf(g_bmax[lane], g_bmax[lane + 32]);
#pragma unroll
    for (int o = 16; o > 0; o >>= 1) m = fmaxf(m, __shfl_down_sync(0xffffffffu, m, o));
    if (lane == 0) { g_scalars[0] = m; g_scalars[2] = m / 0.1f; }
}

// ---------------- K3d: e = expf(sc/0.1 - ymax) (parallel) + block sums ----
__global__ void k_exp()
{
    __shared__ float red[1024];
    int tid = threadIdx.x;
    int idx = blockIdx.x * 1024 + tid;
    float ymax = g_scalars[2];
    float e = expf(g_scores[idx] / 0.1f - ymax);
    g_e[idx] = e;
    float s = blk_add(e, red);
    if (tid == 0) g_bsum[blockIdx.x] = s;
}

// ---------------- K3e: Z = sum of 64 block sums ----------------
__global__ void k_zfin()
{
    int lane = threadIdx.x;                  // 32
    float a = g_bsum[lane] + g_bsum[lane + 32];
#pragma unroll
    for (int o = 16; o > 0; o >>= 1) a += __shfl_down_sync(0xffffffffu, a, o);
    if (lane == 0) g_scalars[1] = a;
}

// ---------------- K4a: build keys + local bitonic sort of 2048 chunks ----
__global__ void k_sort1()
{
    __shared__ unsigned long long s[2048];
    int base = blockIdx.x * 2048;
    int t = threadIdx.x;                 // 1024
    float Z = g_scalars[1];
    {
        float w0 = g_e[base + t] / Z;
        float w1v = g_e[base + t + 1024] / Z;
        s[t] = ((unsigned long long)(~__float_as_uint(w0)) << 32)
             | (unsigned int)((base + t) & (PPB - 1));
        s[t + 1024] = ((unsigned long long)(~__float_as_uint(w1v)) << 32)
             | (unsigned int)((base + t + 1024) & (PPB - 1));
    }
    for (int k = 2; k <= 2048; k <<= 1) {
        for (int j = k >> 1; j > 0; j >>= 1) {
            __syncthreads();
            int i = ((t & ~(j - 1)) << 1) | (t & (j - 1));
            int p = i | j;
            int li = (base + i) & (PPB - 1);
            bool asc = ((li & k) == 0);
            unsigned long long x = s[i], y = s[p];
            if ((x > y) == asc) { s[i] = y; s[p] = x; }
        }
    }
    __syncthreads();
    g_keys[base + t] = s[t];
    g_keys[base + t + 1024] = s[t + 1024];
}

// ---------------- K4c: global compare-exchange stage ----------------
__global__ void k_global_ce(int k, int j)
{
    int t = blockIdx.x * blockDim.x + threadIdx.x;   // 32768
    int b = t >> 13;
    int q = t & 8191;
    int i = ((q & ~(j - 1)) << 1) | (q & (j - 1));
    int gi = b * PPB + i;
    bool asc = ((i & k) == 0);
    unsigned long long x = g_keys[gi], y = g_keys[gi + j];
    if ((x > y) == asc) { g_keys[gi] = y; g_keys[gi + j] = x; }
}

// ---------------- K4d: local merge (j<=1024 within phase k) ----------------
__global__ void k_merge_local(int k)
{
    __shared__ unsigned long long s[2048];
    int base = blockIdx.x * 2048;
    int t = threadIdx.x;
    s[t] = g_keys[base + t];
    s[t + 1024] = g_keys[base + t + 1024];
    for (int j = 1024; j > 0; j >>= 1) {
        __syncthreads();
        int i = ((t & ~(j - 1)) << 1) | (t & (j - 1));
        int p = i | j;
        int li = (base + i) & (PPB - 1);
        bool asc = ((li & k) == 0);
        unsigned long long x = s[i], y = s[p];
        if ((x > y) == asc) { s[i] = y; s[p] = x; }
    }
    __syncthreads();
    g_keys[base + t] = s[t];
    g_keys[base + t + 1024] = s[t + 1024];
}

// ---------------- K5: select top-K per batch + normalized coefficients ----
__global__ void k_select()
{
    __shared__ float red[1024];
    __shared__ float sDen;
    int b = blockIdx.x, tid = threadIdx.x;   // 4 x 1024
    float w4[4];
    float loc = 0.f;
#pragma unroll
    for (int i = 0; i < 4; i++) {
        int r = tid + i * 1024;
        unsigned long long kk = g_keys[b * PPB + r];
        int li = (int)(unsigned int)(kk & 0xffffffffull);
        float w = __uint_as_float(~(unsigned int)(kk >> 32));
        g_gidx[b * TOPK + r] = b * PPB + li;
        w4[i] = w; loc += w;
    }
    float Sb = blk_add(loc, red);
    if (tid == 0) sDen = Sb + 1e-8f;
    __syncthreads();
    float den = sDen;
#pragma unroll
    for (int i = 0; i < 4; i++)
        g_coef[b * TOPK + tid + i * 1024] = w4[i] / den;
}

// ---------------- K7: processor MLP on selected rows, FFMA2 inner ----
__global__ void __launch_bounds__(256, 2) k_proc(
    const float* __restrict__ wp1, const float* __restrict__ bp1,
    const float* __restrict__ wp2, const float* __restrict__ bp2,
    float* __restrict__ out)
{
    __shared__ __align__(16) float sA[32][68];
    __shared__ __align__(16) float sB[32][260];
    __shared__ float sWp2[HID * 4];
    __shared__ float sBp1[HID];
    __shared__ float sC[64];
    __shared__ int   sG[64];

    int tid = threadIdx.x;
    int row0 = blockIdx.x * 64;
    int tx = tid & 15, ty = tid >> 4;

    for (int i = tid; i < HID * 4; i += 256) sWp2[i] = wp2[i];
    sBp1[tid] = bp1[tid];
    if (tid < 64) { sC[tid] = g_coef[row0 + tid]; sG[tid] = g_gidx[row0 + tid]; }
    __syncthreads();

    unsigned long long acc2[4][8];
#pragma unroll
    for (int i = 0; i < 4; i++)
#pragma unroll
        for (int j = 0; j < 8; j++) acc2[i][j] = 0ull;

    for (int kc = 0; kc < HID; kc += 32) {
        __syncthreads();
#pragma unroll
        for (int it = 0; it < 8; it++) {
            int lin = tid + it * 256;        // 0..2047
            int r = lin >> 5, k = lin & 31;
            sA[k][r] = g_pf[sG[r] * HID + kc + k] * sC[r];
        }
#pragma unroll
        for (int it = 0; it < 8; it++) {
            int lin = tid + it * 256;        // float4 index 0..2047
            int k = lin >> 6, c4 = lin & 63;
            *(float4*)&sB[k][c4 * 4] = *(const float4*)&wp1[(kc + k) * HID + c4 * 4];
        }
        __syncthreads();
#pragma unroll
        for (int k = 0; k < 32; k++) {
            float a[4];
            *(float4*)&a[0] = *(const float4*)&sA[k][ty * 4];
            ulonglong2 bv0 = *(const ulonglong2*)&sB[k][tx * 16];
            ulonglong2 bv1 = *(const ulonglong2*)&sB[k][tx * 16 + 4];
            ulonglong2 bv2 = *(const ulonglong2*)&sB[k][tx * 16 + 8];
            ulonglong2 bv3 = *(const ulonglong2*)&sB[k][tx * 16 + 12];
#pragma unroll
            for (int i = 0; i < 4; i++) {
                unsigned long long ad = pack2(a[i], a[i]);
                acc2[i][0] = ffma2(ad, bv0.x, acc2[i][0]);
                acc2[i][1] = ffma2(ad, bv0.y, acc2[i][1]);
                acc2[i][2] = ffma2(ad, bv1.x, acc2[i][2]);
                acc2[i][3] = ffma2(ad, bv1.y, acc2[i][3]);
                acc2[i][4] = ffma2(ad, bv2.x, acc2[i][4]);
                acc2[i][5] = ffma2(ad, bv2.y, acc2[i][5]);
                acc2[i][6] = ffma2(ad, bv3.x, acc2[i][6]);
                acc2[i][7] = ffma2(ad, bv3.y, acc2[i][7]);
            }
        }
    }
#pragma unroll
    for (int i = 0; i < 4; i++) {
        int rl = ty * 4 + i;
        float p0 = 0.f, p1 = 0.f, p2 = 0.f, p3 = 0.f;
#pragma unroll
        for (int j2 = 0; j2 < 8; j2++) {
            float c0, c1;
            unpack2(acc2[i][j2], c0, c1);
            int col0i = tx * 16 + 2 * j2;
            float v0 = fmaxf(c0 + sBp1[col0i], 0.f);
            float v1 = fmaxf(c1 + sBp1[col0i + 1], 0.f);
            p0 = fmaf(v0, sWp2[col0i * 4 + 0], p0);
            p1 = fmaf(v0, sWp2[col0i * 4 + 1], p1);
            p2 = fmaf(v0, sWp2[col0i * 4 + 2], p2);
            p3 = fmaf(v0, sWp2[col0i * 4 + 3], p3);
            p0 = fmaf(v1, sWp2[(col0i + 1) * 4 + 0], p0);
            p1 = fmaf(v1, sWp2[(col0i + 1) * 4 + 1], p1);
            p2 = fmaf(v1, sWp2[(col0i + 1) * 4 + 2], p2);
            p3 = fmaf(v1, sWp2[(col0i + 1) * 4 + 3], p3);
        }
#pragma unroll
        for (int o = 8; o > 0; o >>= 1) {
            p0 += __shfl_down_sync(0xffffffffu, p0, o, 16);
            p1 += __shfl_down_sync(0xffffffffu, p1, o, 16);
            p2 += __shfl_down_sync(0xffffffffu, p2, o, 16);
            p3 += __shfl_down_sync(0xffffffffu, p3, o, 16);
        }
        if (tx == 0) {
            int row = row0 + rl;
            float4 o4;
            o4.x = p0 + bp2[0];
            o4.y = p1 + bp2[1];
            o4.z = p2 + bp2[2];
            o4.w = p3 + bp2[3];
            *(float4*)&out[row * 4] = o4;
        }
    }
}

// ---------------- launch ----------------
extern "C" void kernel_launch(void* const* d_in, const int* in_sizes, int n_in,
                              void* d_out, int out_size)
{
    const float* pts   = (const float*)d_in[0];
    const float* w1    = (const float*)d_in[1];
    const float* b1    = (const float*)d_in[2];
    const float* w2    = (const float*)d_in[3];
    const float* b2    = (const float*)d_in[4];
    const float* ws    = (const float*)d_in[5];
    const float* bs    = (const float*)d_in[6];
    const float* gamma = (const float*)d_in[7];
    const float* beta  = (const float*)d_in[8];
    const float* wp1   = (const float*)d_in[9];
    const float* bp1   = (const float*)d_in[10];
    const float* wp2   = (const float*)d_in[11];
    const float* bp2   = (const float*)d_in[12];
    float* out = (float*)d_out;

    dim3 g1(512, 2);
    k_mlp<<<g1, 256>>>(pts, w1, b1, w2, b2);
    k_srow<<<1024, 64>>>(ws, bs);

    k_bn<<<1, 1024>>>(gamma, beta);
    k_score<<<64, 1024>>>();
    k_gmax<<<1, 32>>>();
    k_exp<<<64, 1024>>>();
    k_zfin<<<1, 32>>>();

    k_sort1<<<32, 1024>>>();
    k_global_ce<<<128, 256>>>(4096, 2048);
    k_merge_local<<<32, 1024>>>(4096);
    k_global_ce<<<128, 256>>>(8192, 4096);
    k_global_ce<<<128, 256>>>(8192, 2048);
    k_merge_local<<<32, 1024>>>(8192);
    k_global_ce<<<128, 256>>>(16384, 8192);
    k_global_ce<<<128, 256>>>(16384, 4096);
    k_global_ce<<<128, 256>>>(16384, 2048);
    k_merge_local<<<32, 1024>>>(16384);

    k_select<<<NB, 1024>>>();
    k_proc<<<256, 256>>>(wp1, bp1, wp2, bp2, out);
}